// round 14
// baseline (speedup 1.0000x reference)
#include <cuda_runtime.h>
#include <cuda_fp16.h>
#include <mma.h>
#include <cstdint>

using namespace nvcuda;

#define NN 50000
#define NE 800000
#define DIM 128
#define NCLS 10
#define NG 64
#define NT ((NN + 127) / 128)       // 391 M-tiles
#define SB ((NN + 255) / 256)       // 196 scan blocks

// ---------------- static device scratch ----------------
__device__ __align__(16) uint2 g_B16[DIM * 32];        // fp16 W (128x128)
__device__ __align__(16) float g_h2[NN * DIM];         // relu(A@W + b)
__device__ float g_outnorm[NN];
__device__ int   g_outdeg_i[NN];
__device__ int   g_indeg_i[NN];
__device__ int   g_rowptr[NN + 1];
__device__ int   g_cursor[NN];
__device__ int   g_esrc[NE];
__device__ int   g_start[NG + 1];
__device__ int   g_bsum[SB];
__device__ int   g_is64;

// ---------------- helpers ----------------
__device__ __forceinline__ int idx_at(const void* buf, int i, int is64) {
    return is64 ? (int)((const long long*)buf)[i] : ((const int*)buf)[i];
}

// per-block index width detection: if int64, odd words are all zero
__device__ __forceinline__ int detect_local(const void* src, int* sflag) {
    if (threadIdx.x < 32) {
        const int* p = (const int*)src;
        int z = (p[2 * threadIdx.x + 1] == 0);
        unsigned m = __ballot_sync(0xffffffffu, z);
        if (threadIdx.x == 0) *sflag = (m == 0xffffffffu);
    }
    __syncthreads();
    return *sflag;
}

// ---- fused: detect + zero degs + graph bounds + W->fp16 ----
__global__ void zero_bounds_kernel(const void* src, const void* gids,
                                   const float* __restrict__ W) {
    __shared__ int sflag;
    int is64 = detect_local(src, &sflag);
    int i = blockIdx.x * blockDim.x + threadIdx.x;

    if (i == 0) g_is64 = is64;

    if (i < NN) { g_outdeg_i[i] = 0; g_indeg_i[i] = 0; }

    // W fp32 -> fp16 (once)
    if (i < DIM * 32) {
        float4 v = ((const float4*)W)[i];
        __half2 h0 = __floats2half2_rn(v.x, v.y);
        __half2 h1 = __floats2half2_rn(v.z, v.w);
        uint2 u;
        u.x = *reinterpret_cast<unsigned*>(&h0);
        u.y = *reinterpret_cast<unsigned*>(&h1);
        g_B16[i] = u;
    }

    if (i < NN) {   // graph boundaries (graph_ids sorted ascending)
        int g = idx_at(gids, i, is64);
        int gp = (i > 0) ? idx_at(gids, i - 1, is64) : -1;
        for (int gg = gp + 1; gg <= g; gg++) g_start[gg] = i;
        if (i == NN - 1)
            for (int gg = g + 1; gg <= NG; gg++) g_start[gg] = NN;
    }
}

// ---------------- degrees (both, int atomics) ----------------
__global__ void degree_kernel(const void* src, const void* dst) {
    int e = blockIdx.x * blockDim.x + threadIdx.x;
    if (e >= NE) return;
    int is64 = g_is64;
    atomicAdd(&g_outdeg_i[idx_at(src, e, is64)], 1);
    atomicAdd(&g_indeg_i[idx_at(dst, e, is64)], 1);
}

// ---------------- hierarchical scan: partial -> apply (spine fused) ----------
__global__ void scan_partial_kernel() {
    int i = blockIdx.x * 256 + threadIdx.x;
    int d = (i < NN) ? g_indeg_i[i] : 0;
    #pragma unroll
    for (int off = 16; off > 0; off >>= 1)
        d += __shfl_down_sync(0xffffffffu, d, off);
    __shared__ int ws[8];
    int wid = threadIdx.x >> 5, lane = threadIdx.x & 31;
    if (lane == 0) ws[wid] = d;
    __syncthreads();
    if (threadIdx.x < 8) {
        int v = ws[threadIdx.x];
        #pragma unroll
        for (int off = 4; off > 0; off >>= 1)
            v += __shfl_down_sync(0xffu, v, off);
        if (threadIdx.x == 0) g_bsum[blockIdx.x] = v;
    }
}

__global__ void scan_apply_kernel() {
    int t = threadIdx.x;
    int lane = t & 31, wid = t >> 5;

    __shared__ int rs[8];
    __shared__ int s_off;
    int acc = 0;
    for (int j = t; j < (int)blockIdx.x; j += 256) acc += g_bsum[j];
    #pragma unroll
    for (int off = 16; off > 0; off >>= 1)
        acc += __shfl_down_sync(0xffffffffu, acc, off);
    if (lane == 0) rs[wid] = acc;
    __syncthreads();
    if (t < 8) {
        int v = rs[t];
        #pragma unroll
        for (int off = 4; off > 0; off >>= 1)
            v += __shfl_down_sync(0xffu, v, off);
        if (t == 0) s_off = v;
    }
    __syncthreads();

    int i = blockIdx.x * 256 + t;
    int d = (i < NN) ? g_indeg_i[i] : 0;
    int v = d;
    #pragma unroll
    for (int off = 1; off < 32; off <<= 1) {
        int n = __shfl_up_sync(0xffffffffu, v, off);
        if (lane >= off) v += n;
    }
    __shared__ int ws[8];
    if (lane == 31) ws[wid] = v;
    __syncthreads();
    if (t < 8) {
        int s = ws[t];
        #pragma unroll
        for (int off = 1; off < 8; off <<= 1) {
            int n = __shfl_up_sync(0xffu, s, off);
            if (t >= off) s += n;
        }
        ws[t] = s;
    }
    __syncthreads();
    int inc = v + (wid > 0 ? ws[wid - 1] : 0) + s_off;
    int exc = inc - d;
    if (i < NN) {
        g_rowptr[i] = exc;
        g_cursor[i] = exc;
        g_outnorm[i] = rsqrtf(fmaxf((float)g_outdeg_i[i], 1.f));
    }
    if (i == NN) g_rowptr[NN] = NE;
}

// ---------------- fill dst-sorted edge list ----------------
__global__ void fill_kernel(const void* src, const void* dst) {
    int e = blockIdx.x * blockDim.x + threadIdx.x;
    if (e >= NE) return;
    int is64 = g_is64;
    int s = idx_at(src, e, is64);
    int d = idx_at(dst, e, is64);
    int pos = atomicAdd(&g_cursor[d], 1);
    g_esrc[pos] = s;
}

// ------ fused gather + WMMA fp16 GEMM: h2 = relu((norm-agg feat) @ W + b) ----
// Each CTA owns 128 dst rows: 8 warps gather 16 rows each straight into smem A
// (fp16), then 128x128x128 HMMA. smem 70144 B -> 3 CTAs/SM: gather phase of one
// CTA overlaps MMA of the others.
#define HPAD 136                       // half stride per smem row (272 B)
#define CPAD 132                       // fp32 stride for epilogue reuse
#define SMEM_GEMM (512 + 2 * 128 * HPAD * 2)   // 70144 B

__global__ __launch_bounds__(256)
void gather_gemm_kernel(const float* __restrict__ feat,
                        const float* __restrict__ bias) {
    extern __shared__ unsigned char smraw[];
    float*  sBias = (float*)smraw;                    // 128 floats
    __half* As = (__half*)(smraw + 512);              // 128 x 136 half
    __half* Bs = As + 128 * HPAD;                     // 128 x 136 half (W[k][n])
    float*  Cs = (float*)(smraw + 512);               // epilogue reuse (128x132 f32)

    int tid = threadIdx.x;
    int wid = tid >> 5;
    int lane = tid & 31;
    int m0 = blockIdx.x * 128;

    if (tid < 128) sBias[tid] = bias[tid];

    // B tile: fp16 W from gmem (independent of gather; issue first)
    {
        #pragma unroll
        for (int i = 0; i < 16; i++) {
            int idx = tid + i * 256;
            int r = idx >> 5, c = idx & 31;
            *reinterpret_cast<uint2*>(Bs + r * HPAD + c * 4) = g_B16[idx];
        }
    }

    // Gather phase: warp wid handles rows [wid*16, wid*16+16)
    const float4* f4 = (const float4*)feat;
    for (int rr = 0; rr < 16; rr++) {
        int r = wid * 16 + rr;
        int w = m0 + r;
        float4 a0 = make_float4(0.f, 0.f, 0.f, 0.f);
        float4 a1 = make_float4(0.f, 0.f, 0.f, 0.f);
        float inn = 0.f;
        if (w < NN) {
            int beg = g_rowptr[w], end = g_rowptr[w + 1];
            for (int base = beg; base < end; base += 32) {
                int n = min(32, end - base);
                int sl = (base + lane < end) ? g_esrc[base + lane] : 0;
                int j = 0;
                for (; j + 4 <= n; j += 4) {
                    int s0 = __shfl_sync(0xffffffffu, sl, j);
                    int s1 = __shfl_sync(0xffffffffu, sl, j + 1);
                    int s2 = __shfl_sync(0xffffffffu, sl, j + 2);
                    int s3 = __shfl_sync(0xffffffffu, sl, j + 3);
                    float on0 = g_outnorm[s0], on1 = g_outnorm[s1];
                    float on2 = g_outnorm[s2], on3 = g_outnorm[s3];
                    float4 v0 = f4[s0 * 32 + lane];
                    float4 v1 = f4[s1 * 32 + lane];
                    float4 v2 = f4[s2 * 32 + lane];
                    float4 v3 = f4[s3 * 32 + lane];
                    a0.x += v0.x * on0; a0.y += v0.y * on0; a0.z += v0.z * on0; a0.w += v0.w * on0;
                    a1.x += v1.x * on1; a1.y += v1.y * on1; a1.z += v1.z * on1; a1.w += v1.w * on1;
                    a0.x += v2.x * on2; a0.y += v2.y * on2; a0.z += v2.z * on2; a0.w += v2.w * on2;
                    a1.x += v3.x * on3; a1.y += v3.y * on3; a1.z += v3.z * on3; a1.w += v3.w * on3;
                }
                for (; j < n; j++) {
                    int s0 = __shfl_sync(0xffffffffu, sl, j);
                    float on0 = g_outnorm[s0];
                    float4 v0 = f4[s0 * 32 + lane];
                    a0.x += v0.x * on0; a0.y += v0.y * on0; a0.z += v0.z * on0; a0.w += v0.w * on0;
                }
            }
            inn = rsqrtf(fmaxf((float)(end - beg), 1.f));
        }
        __half2 h0 = __floats2half2_rn((a0.x + a1.x) * inn, (a0.y + a1.y) * inn);
        __half2 h1 = __floats2half2_rn((a0.z + a1.z) * inn, (a0.w + a1.w) * inn);
        uint2 pk;
        pk.x = *reinterpret_cast<unsigned*>(&h0);
        pk.y = *reinterpret_cast<unsigned*>(&h1);
        *reinterpret_cast<uint2*>(As + r * HPAD + lane * 4) = pk;
    }
    __syncthreads();

    // MMA phase
    int wm = (wid >> 1) * 32;   // 0,32,64,96
    int wn = (wid & 1) * 64;    // 0,64

    wmma::fragment<wmma::accumulator, 16, 16, 16, float> acc[2][4];
    #pragma unroll
    for (int i = 0; i < 2; i++)
        #pragma unroll
        for (int j = 0; j < 4; j++)
            wmma::fill_fragment(acc[i][j], 0.f);

    #pragma unroll
    for (int k0 = 0; k0 < DIM; k0 += 16) {
        wmma::fragment<wmma::matrix_a, 16, 16, 16, __half, wmma::row_major> a[2];
        wmma::fragment<wmma::matrix_b, 16, 16, 16, __half, wmma::row_major> b[4];
        #pragma unroll
        for (int i = 0; i < 2; i++)
            wmma::load_matrix_sync(a[i], As + (wm + i * 16) * HPAD + k0, HPAD);
        #pragma unroll
        for (int j = 0; j < 4; j++)
            wmma::load_matrix_sync(b[j], Bs + k0 * HPAD + wn + j * 16, HPAD);
        #pragma unroll
        for (int i = 0; i < 2; i++)
            #pragma unroll
            for (int j = 0; j < 4; j++)
                wmma::mma_sync(acc[i][j], a[i], b[j], acc[i][j]);
    }
    __syncthreads();   // done reading As/Bs; Cs aliases them

    #pragma unroll
    for (int i = 0; i < 2; i++)
        #pragma unroll
        for (int j = 0; j < 4; j++)
            wmma::store_matrix_sync(Cs + (wm + i * 16) * CPAD + wn + j * 16,
                                    acc[i][j], CPAD, wmma::mem_row_major);
    __syncthreads();

    const float4* c4 = (const float4*)Cs;
    float4* h4 = (float4*)g_h2;
    #pragma unroll
    for (int i = 0; i < 16; i++) {
        int idx = tid + i * 256;
        int r = idx >> 5, c = idx & 31;
        int grow = m0 + r;
        if (grow < NN) {
            float4 v = c4[r * 33 + c];
            float4 o;
            o.x = fmaxf(v.x + sBias[c * 4 + 0], 0.f);
            o.y = fmaxf(v.y + sBias[c * 4 + 1], 0.f);
            o.z = fmaxf(v.z + sBias[c * 4 + 2], 0.f);
            o.w = fmaxf(v.w + sBias[c * 4 + 3], 0.f);
            h4[(size_t)grow * 32 + c] = o;
        }
    }
}

// ---------------- segment-mean pool + head GEMM -----------------------------
// 1024 threads: 8 row-groups x 128 cols, then reduce.
__global__ void pool_head_kernel(const float* __restrict__ Wh,
                                 const float* __restrict__ bh,
                                 float* __restrict__ out) {
    __shared__ float part[8][DIM];
    __shared__ float pooled[DIM];
    int g = blockIdx.x;
    int c = threadIdx.x & 127;
    int rg = threadIdx.x >> 7;   // 0..7
    int s = g_start[g], e = g_start[g + 1];
    float sum = 0.f;
    for (int r = s + rg; r < e; r += 8) sum += g_h2[(size_t)r * DIM + c];
    part[rg][c] = sum;
    __syncthreads();
    if (rg == 0) {
        float cnt = fmaxf((float)(e - s), 1.f);
        float tot = part[0][c] + part[1][c] + part[2][c] + part[3][c]
                  + part[4][c] + part[5][c] + part[6][c] + part[7][c];
        pooled[c] = tot / cnt;
    }
    __syncthreads();
    if (rg == 0 && c < NCLS) {
        float acc = bh[c];
        #pragma unroll 4
        for (int d = 0; d < DIM; d++) acc += pooled[d] * Wh[d * NCLS + c];
        out[g * NCLS + c] = acc;
    }
}

// ---------------- launch ----------------
extern "C" void kernel_launch(void* const* d_in, const int* in_sizes, int n_in,
                              void* d_out, int out_size) {
    const float* feat = (const float*)d_in[0];
    const void*  src  = d_in[1];
    const void*  dst  = d_in[2];
    const void*  gids = d_in[3];
    const float* W    = (const float*)d_in[4];
    const float* b    = (const float*)d_in[5];
    const float* Wh   = (const float*)d_in[6];
    const float* bh   = (const float*)d_in[7];
    float* out = (float*)d_out;

    cudaFuncSetAttribute(gather_gemm_kernel,
                         cudaFuncAttributeMaxDynamicSharedMemorySize, SMEM_GEMM);

    zero_bounds_kernel<<<(NN + 255) / 256, 256>>>(src, gids, W);
    degree_kernel<<<(NE + 255) / 256, 256>>>(src, dst);
    scan_partial_kernel<<<SB, 256>>>();
    scan_apply_kernel<<<SB + 1, 256>>>();
    fill_kernel<<<(NE + 255) / 256, 256>>>(src, dst);
    gather_gemm_kernel<<<NT, 256, SMEM_GEMM>>>(feat, b);
    pool_head_kernel<<<NG, 1024>>>(Wh, bh, out);
}

// round 15
// speedup vs baseline: 1.3189x; 1.3189x over previous
#include <cuda_runtime.h>
#include <cuda_fp16.h>
#include <mma.h>
#include <cstdint>

using namespace nvcuda;

#define NN 50000
#define NE 800000
#define DIM 128
#define NCLS 10
#define NG 64
#define NT ((NN + 127) / 128)       // 391 M-tiles
#define SB ((NN + 255) / 256)       // 196 scan blocks

// ---------------- static device scratch ----------------
// fp16 A: one row = 128 halfs = 256 B = 32 uint2. Full buffer NT*128 rows.
__device__ __align__(16) uint2 g_A16[NT * 128 * 32];
__device__ __align__(16) uint2 g_B16[DIM * 32];        // fp16 W (128x128)
__device__ __align__(16) float g_h2[NN * DIM];         // relu(A@W + b)
__device__ float g_outnorm[NN];
__device__ int   g_outdeg_i[NN];
__device__ int   g_indeg_i[NN];
__device__ int   g_rowptr[NN + 1];
__device__ int   g_cursor[NN];
__device__ int   g_esrc[NE];
__device__ int   g_start[NG + 1];
__device__ int   g_bsum[SB];
__device__ int   g_is64;

// ---------------- helpers ----------------
__device__ __forceinline__ int idx_at(const void* buf, int i, int is64) {
    return is64 ? (int)((const long long*)buf)[i] : ((const int*)buf)[i];
}

// per-block index width detection: if int64, odd words are all zero
__device__ __forceinline__ int detect_local(const void* src, int* sflag) {
    if (threadIdx.x < 32) {
        const int* p = (const int*)src;
        int z = (p[2 * threadIdx.x + 1] == 0);
        unsigned m = __ballot_sync(0xffffffffu, z);
        if (threadIdx.x == 0) *sflag = (m == 0xffffffffu);
    }
    __syncthreads();
    return *sflag;
}

// ---- fused: detect + zero degs + zero A tail + graph bounds + W->fp16 ----
__global__ void zero_bounds_kernel(const void* src, const void* gids,
                                   const float* __restrict__ W) {
    __shared__ int sflag;
    int is64 = detect_local(src, &sflag);
    int i = blockIdx.x * blockDim.x + threadIdx.x;

    if (i == 0) g_is64 = is64;

    if (i < NN) { g_outdeg_i[i] = 0; g_indeg_i[i] = 0; }
    // zero fp16 A tail rows: (NT*128 - NN) rows * 32 uint2 = 6144 uint2
    const int TAILU2 = (NT * 128 - NN) * 32;
    if (i < TAILU2) g_A16[(size_t)NN * 32 + i] = make_uint2(0u, 0u);

    // W fp32 -> fp16 (once)
    if (i < DIM * 32) {
        float4 v = ((const float4*)W)[i];
        __half2 h0 = __floats2half2_rn(v.x, v.y);
        __half2 h1 = __floats2half2_rn(v.z, v.w);
        uint2 u;
        u.x = *reinterpret_cast<unsigned*>(&h0);
        u.y = *reinterpret_cast<unsigned*>(&h1);
        g_B16[i] = u;
    }

    if (i < NN) {   // graph boundaries (graph_ids sorted ascending)
        int g = idx_at(gids, i, is64);
        int gp = (i > 0) ? idx_at(gids, i - 1, is64) : -1;
        for (int gg = gp + 1; gg <= g; gg++) g_start[gg] = i;
        if (i == NN - 1)
            for (int gg = g + 1; gg <= NG; gg++) g_start[gg] = NN;
    }
}

// ---------------- degrees (both, int atomics) ----------------
__global__ void degree_kernel(const void* src, const void* dst) {
    int e = blockIdx.x * blockDim.x + threadIdx.x;
    if (e >= NE) return;
    int is64 = g_is64;
    atomicAdd(&g_outdeg_i[idx_at(src, e, is64)], 1);
    atomicAdd(&g_indeg_i[idx_at(dst, e, is64)], 1);
}

// ---------------- hierarchical scan: partial -> apply (spine fused) ----------
__global__ void scan_partial_kernel() {
    int i = blockIdx.x * 256 + threadIdx.x;
    int d = (i < NN) ? g_indeg_i[i] : 0;
    #pragma unroll
    for (int off = 16; off > 0; off >>= 1)
        d += __shfl_down_sync(0xffffffffu, d, off);
    __shared__ int ws[8];
    int wid = threadIdx.x >> 5, lane = threadIdx.x & 31;
    if (lane == 0) ws[wid] = d;
    __syncthreads();
    if (threadIdx.x < 8) {
        int v = ws[threadIdx.x];
        #pragma unroll
        for (int off = 4; off > 0; off >>= 1)
            v += __shfl_down_sync(0xffu, v, off);
        if (threadIdx.x == 0) g_bsum[blockIdx.x] = v;
    }
}

__global__ void scan_apply_kernel() {
    int t = threadIdx.x;
    int lane = t & 31, wid = t >> 5;

    __shared__ int rs[8];
    __shared__ int s_off;
    int acc = 0;
    for (int j = t; j < (int)blockIdx.x; j += 256) acc += g_bsum[j];
    #pragma unroll
    for (int off = 16; off > 0; off >>= 1)
        acc += __shfl_down_sync(0xffffffffu, acc, off);
    if (lane == 0) rs[wid] = acc;
    __syncthreads();
    if (t < 8) {
        int v = rs[t];
        #pragma unroll
        for (int off = 4; off > 0; off >>= 1)
            v += __shfl_down_sync(0xffu, v, off);
        if (t == 0) s_off = v;
    }
    __syncthreads();

    int i = blockIdx.x * 256 + t;
    int d = (i < NN) ? g_indeg_i[i] : 0;
    int v = d;
    #pragma unroll
    for (int off = 1; off < 32; off <<= 1) {
        int n = __shfl_up_sync(0xffffffffu, v, off);
        if (lane >= off) v += n;
    }
    __shared__ int ws[8];
    if (lane == 31) ws[wid] = v;
    __syncthreads();
    if (t < 8) {
        int s = ws[t];
        #pragma unroll
        for (int off = 1; off < 8; off <<= 1) {
            int n = __shfl_up_sync(0xffu, s, off);
            if (t >= off) s += n;
        }
        ws[t] = s;
    }
    __syncthreads();
    int inc = v + (wid > 0 ? ws[wid - 1] : 0) + s_off;
    int exc = inc - d;
    if (i < NN) {
        g_rowptr[i] = exc;
        g_cursor[i] = exc;
        g_outnorm[i] = rsqrtf(fmaxf((float)g_outdeg_i[i], 1.f));
    }
    if (i == NN) g_rowptr[NN] = NE;
}

// ---------------- fill dst-sorted edge list ----------------
__global__ void fill_kernel(const void* src, const void* dst) {
    int e = blockIdx.x * blockDim.x + threadIdx.x;
    if (e >= NE) return;
    int is64 = g_is64;
    int s = idx_at(src, e, is64);
    int d = idx_at(dst, e, is64);
    int pos = atomicAdd(&g_cursor[d], 1);
    g_esrc[pos] = s;
}

// ------- gather: one warp per dst node, shfl indices, 4 rows in flight -------
// A16[d] = fp16( in_norm(d) * sum_{e} out_norm(src) * feat[src] )
__global__ void gather_kernel(const float* __restrict__ feat) {
    int w = (blockIdx.x * blockDim.x + threadIdx.x) >> 5;
    if (w >= NN) return;
    int lane = threadIdx.x & 31;
    int beg = g_rowptr[w], end = g_rowptr[w + 1];

    const float4* f4 = (const float4*)feat;
    float4 a0 = make_float4(0.f, 0.f, 0.f, 0.f);
    float4 a1 = make_float4(0.f, 0.f, 0.f, 0.f);

    for (int base = beg; base < end; base += 32) {
        int n = min(32, end - base);
        int sl = (base + lane < end) ? g_esrc[base + lane] : 0;
        int j = 0;
        for (; j + 4 <= n; j += 4) {
            int s0 = __shfl_sync(0xffffffffu, sl, j);
            int s1 = __shfl_sync(0xffffffffu, sl, j + 1);
            int s2 = __shfl_sync(0xffffffffu, sl, j + 2);
            int s3 = __shfl_sync(0xffffffffu, sl, j + 3);
            float on0 = g_outnorm[s0], on1 = g_outnorm[s1];
            float on2 = g_outnorm[s2], on3 = g_outnorm[s3];
            float4 v0 = f4[s0 * 32 + lane];
            float4 v1 = f4[s1 * 32 + lane];
            float4 v2 = f4[s2 * 32 + lane];
            float4 v3 = f4[s3 * 32 + lane];
            a0.x += v0.x * on0; a0.y += v0.y * on0; a0.z += v0.z * on0; a0.w += v0.w * on0;
            a1.x += v1.x * on1; a1.y += v1.y * on1; a1.z += v1.z * on1; a1.w += v1.w * on1;
            a0.x += v2.x * on2; a0.y += v2.y * on2; a0.z += v2.z * on2; a0.w += v2.w * on2;
            a1.x += v3.x * on3; a1.y += v3.y * on3; a1.z += v3.z * on3; a1.w += v3.w * on3;
        }
        for (; j < n; j++) {
            int s0 = __shfl_sync(0xffffffffu, sl, j);
            float on0 = g_outnorm[s0];
            float4 v0 = f4[s0 * 32 + lane];
            a0.x += v0.x * on0; a0.y += v0.y * on0; a0.z += v0.z * on0; a0.w += v0.w * on0;
        }
    }
    float inn = rsqrtf(fmaxf((float)(end - beg), 1.f));
    __half2 h0 = __floats2half2_rn((a0.x + a1.x) * inn, (a0.y + a1.y) * inn);
    __half2 h1 = __floats2half2_rn((a0.z + a1.z) * inn, (a0.w + a1.w) * inn);
    uint2 pk;
    pk.x = *reinterpret_cast<unsigned*>(&h0);
    pk.y = *reinterpret_cast<unsigned*>(&h1);
    g_A16[(size_t)w * 32 + lane] = pk;
}

// ---------------- WMMA fp16 GEMM: h2 = relu(A @ W + b) ----------------
// 128x128 tile, full K=128 in smem (fp16). 8 warps, warp-tile 32x64 (2x4 frags).
// smem: bias 512B + A 128x136 half + B 128x136 half = 70144 B -> 3 CTAs/SM.
#define HPAD 136                       // half stride per smem row (272 B)
#define CPAD 132                       // fp32 stride for epilogue reuse
#define SMEM_GEMM (512 + 2 * 128 * HPAD * 2)   // 70144 B

__global__ __launch_bounds__(256)
void gemm_tc_kernel(const float* __restrict__ bias) {
    extern __shared__ unsigned char smraw[];
    float*  sBias = (float*)smraw;                    // 128 floats
    __half* As = (__half*)(smraw + 512);              // 128 x 136 half
    __half* Bs = As + 128 * HPAD;                     // 128 x 136 half (W[k][n])
    float*  Cs = (float*)(smraw + 512);               // epilogue reuse (128x132 f32)

    int tid = threadIdx.x;
    int wid = tid >> 5;
    int m0 = blockIdx.x * 128;

    if (tid < 128) sBias[tid] = bias[tid];

    // A + B tiles: fp16 from gmem, 4096 uint2 each
    {
        const uint2* pa = g_A16 + (size_t)m0 * 32;
        #pragma unroll
        for (int i = 0; i < 16; i++) {
            int idx = tid + i * 256;      // 0..4095
            int r = idx >> 5, c = idx & 31;
            *reinterpret_cast<uint2*>(As + r * HPAD + c * 4) = pa[idx];
            *reinterpret_cast<uint2*>(Bs + r * HPAD + c * 4) = g_B16[idx];
        }
    }
    __syncthreads();

    int wm = (wid >> 1) * 32;   // 0,32,64,96
    int wn = (wid & 1) * 64;    // 0,64

    wmma::fragment<wmma::accumulator, 16, 16, 16, float> acc[2][4];
    #pragma unroll
    for (int i = 0; i < 2; i++)
        #pragma unroll
        for (int j = 0; j < 4; j++)
            wmma::fill_fragment(acc[i][j], 0.f);

    #pragma unroll
    for (int k0 = 0; k0 < DIM; k0 += 16) {
        wmma::fragment<wmma::matrix_a, 16, 16, 16, __half, wmma::row_major> a[2];
        wmma::fragment<wmma::matrix_b, 16, 16, 16, __half, wmma::row_major> b[4];
        #pragma unroll
        for (int i = 0; i < 2; i++)
            wmma::load_matrix_sync(a[i], As + (wm + i * 16) * HPAD + k0, HPAD);
        #pragma unroll
        for (int j = 0; j < 4; j++)
            wmma::load_matrix_sync(b[j], Bs + k0 * HPAD + wn + j * 16, HPAD);
        #pragma unroll
        for (int i = 0; i < 2; i++)
            #pragma unroll
            for (int j = 0; j < 4; j++)
                wmma::mma_sync(acc[i][j], a[i], b[j], acc[i][j]);
    }
    __syncthreads();   // done reading As/Bs; Cs aliases them

    #pragma unroll
    for (int i = 0; i < 2; i++)
        #pragma unroll
        for (int j = 0; j < 4; j++)
            wmma::store_matrix_sync(Cs + (wm + i * 16) * CPAD + wn + j * 16,
                                    acc[i][j], CPAD, wmma::mem_row_major);
    __syncthreads();

    const float4* c4 = (const float4*)Cs;
    float4* h4 = (float4*)g_h2;
    #pragma unroll
    for (int i = 0; i < 16; i++) {
        int idx = tid + i * 256;
        int r = idx >> 5, c = idx & 31;
        int grow = m0 + r;
        if (grow < NN) {
            float4 v = c4[r * 33 + c];
            float4 o;
            o.x = fmaxf(v.x + sBias[c * 4 + 0], 0.f);
            o.y = fmaxf(v.y + sBias[c * 4 + 1], 0.f);
            o.z = fmaxf(v.z + sBias[c * 4 + 2], 0.f);
            o.w = fmaxf(v.w + sBias[c * 4 + 3], 0.f);
            h4[(size_t)grow * 32 + c] = o;
        }
    }
}

// ---------------- segment-mean pool + head GEMM -----------------------------
// 1024 threads: 8 row-groups x 128 cols, then reduce.
__global__ void pool_head_kernel(const float* __restrict__ Wh,
                                 const float* __restrict__ bh,
                                 float* __restrict__ out) {
    __shared__ float part[8][DIM];
    __shared__ float pooled[DIM];
    int g = blockIdx.x;
    int c = threadIdx.x & 127;
    int rg = threadIdx.x >> 7;   // 0..7
    int s = g_start[g], e = g_start[g + 1];
    float sum = 0.f;
    for (int r = s + rg; r < e; r += 8) sum += g_h2[(size_t)r * DIM + c];
    part[rg][c] = sum;
    __syncthreads();
    if (rg == 0) {
        float cnt = fmaxf((float)(e - s), 1.f);
        float tot = part[0][c] + part[1][c] + part[2][c] + part[3][c]
                  + part[4][c] + part[5][c] + part[6][c] + part[7][c];
        pooled[c] = tot / cnt;
    }
    __syncthreads();
    if (rg == 0 && c < NCLS) {
        float acc = bh[c];
        #pragma unroll 4
        for (int d = 0; d < DIM; d++) acc += pooled[d] * Wh[d * NCLS + c];
        out[g * NCLS + c] = acc;
    }
}

// ---------------- launch ----------------
extern "C" void kernel_launch(void* const* d_in, const int* in_sizes, int n_in,
                              void* d_out, int out_size) {
    const float* feat = (const float*)d_in[0];
    const void*  src  = d_in[1];
    const void*  dst  = d_in[2];
    const void*  gids = d_in[3];
    const float* W    = (const float*)d_in[4];
    const float* b    = (const float*)d_in[5];
    const float* Wh   = (const float*)d_in[6];
    const float* bh   = (const float*)d_in[7];
    float* out = (float*)d_out;

    cudaFuncSetAttribute(gemm_tc_kernel,
                         cudaFuncAttributeMaxDynamicSharedMemorySize, SMEM_GEMM);

    zero_bounds_kernel<<<(NN + 255) / 256, 256>>>(src, gids, W);
    degree_kernel<<<(NE + 255) / 256, 256>>>(src, dst);
    scan_partial_kernel<<<SB, 256>>>();
    scan_apply_kernel<<<SB + 1, 256>>>();
    fill_kernel<<<(NE + 255) / 256, 256>>>(src, dst);
    gather_kernel<<<(NN * 32 + 255) / 256, 256>>>(feat);
    gemm_tc_kernel<<<NT, 256, SMEM_GEMM>>>(b);
    pool_head_kernel<<<NG, 1024>>>(Wh, bh, out);
}

// round 16
// speedup vs baseline: 1.4584x; 1.1058x over previous
#include <cuda_runtime.h>
#include <cuda_fp16.h>
#include <mma.h>
#include <cstdint>

using namespace nvcuda;

#define NN 50000
#define NE 800000
#define DIM 128
#define NCLS 10
#define NG 64
#define NT ((NN + 127) / 128)       // 391 M-tiles
#define SB ((NN + 255) / 256)       // 196 scan blocks

// ---------------- static device scratch ----------------
// fp16 A: one row = 128 halfs = 256 B = 32 uint2. Full buffer NT*128 rows.
__device__ __align__(16) uint2 g_A16[NT * 128 * 32];
__device__ __align__(16) uint2 g_B16[DIM * 32];        // fp16 W (128x128)
__device__ float g_pool[NG * DIM];                     // pooled sums (atomic accum)
__device__ float g_outnorm[NN];
__device__ int   g_outdeg_i[NN];
__device__ int   g_indeg_i[NN];
__device__ int   g_rowptr[NN + 1];
__device__ int   g_cursor[NN];
__device__ int   g_esrc[NE];
__device__ int   g_start[NG + 1];
__device__ int   g_bsum[SB];
__device__ int   g_is64;

// ---------------- helpers ----------------
__device__ __forceinline__ int idx_at(const void* buf, int i, int is64) {
    return is64 ? (int)((const long long*)buf)[i] : ((const int*)buf)[i];
}

// per-block index width detection: if int64, odd words are all zero
__device__ __forceinline__ int detect_local(const void* src, int* sflag) {
    if (threadIdx.x < 32) {
        const int* p = (const int*)src;
        int z = (p[2 * threadIdx.x + 1] == 0);
        unsigned m = __ballot_sync(0xffffffffu, z);
        if (threadIdx.x == 0) *sflag = (m == 0xffffffffu);
    }
    __syncthreads();
    return *sflag;
}

// ---- fused: detect + zero degs/pool + zero A tail + graph bounds + W->fp16 ----
__global__ void zero_bounds_kernel(const void* src, const void* gids,
                                   const float* __restrict__ W) {
    __shared__ int sflag;
    int is64 = detect_local(src, &sflag);
    int i = blockIdx.x * blockDim.x + threadIdx.x;

    if (i == 0) g_is64 = is64;

    if (i < NN) { g_outdeg_i[i] = 0; g_indeg_i[i] = 0; }
    if (i < NG * DIM) g_pool[i] = 0.f;
    // zero fp16 A tail rows: (NT*128 - NN) rows * 32 uint2 = 6144 uint2
    const int TAILU2 = (NT * 128 - NN) * 32;
    if (i < TAILU2) g_A16[(size_t)NN * 32 + i] = make_uint2(0u, 0u);

    // W fp32 -> fp16 (once)
    if (i < DIM * 32) {
        float4 v = ((const float4*)W)[i];
        __half2 h0 = __floats2half2_rn(v.x, v.y);
        __half2 h1 = __floats2half2_rn(v.z, v.w);
        uint2 u;
        u.x = *reinterpret_cast<unsigned*>(&h0);
        u.y = *reinterpret_cast<unsigned*>(&h1);
        g_B16[i] = u;
    }

    if (i < NN) {   // graph boundaries (graph_ids sorted ascending)
        int g = idx_at(gids, i, is64);
        int gp = (i > 0) ? idx_at(gids, i - 1, is64) : -1;
        for (int gg = gp + 1; gg <= g; gg++) g_start[gg] = i;
        if (i == NN - 1)
            for (int gg = g + 1; gg <= NG; gg++) g_start[gg] = NN;
    }
}

// ---------------- degrees (both, int atomics) ----------------
__global__ void degree_kernel(const void* src, const void* dst) {
    int e = blockIdx.x * blockDim.x + threadIdx.x;
    if (e >= NE) return;
    int is64 = g_is64;
    atomicAdd(&g_outdeg_i[idx_at(src, e, is64)], 1);
    atomicAdd(&g_indeg_i[idx_at(dst, e, is64)], 1);
}

// ---------------- hierarchical scan: partial -> apply (spine fused) ----------
__global__ void scan_partial_kernel() {
    int i = blockIdx.x * 256 + threadIdx.x;
    int d = (i < NN) ? g_indeg_i[i] : 0;
    #pragma unroll
    for (int off = 16; off > 0; off >>= 1)
        d += __shfl_down_sync(0xffffffffu, d, off);
    __shared__ int ws[8];
    int wid = threadIdx.x >> 5, lane = threadIdx.x & 31;
    if (lane == 0) ws[wid] = d;
    __syncthreads();
    if (threadIdx.x < 8) {
        int v = ws[threadIdx.x];
        #pragma unroll
        for (int off = 4; off > 0; off >>= 1)
            v += __shfl_down_sync(0xffu, v, off);
        if (threadIdx.x == 0) g_bsum[blockIdx.x] = v;
    }
}

__global__ void scan_apply_kernel() {
    int t = threadIdx.x;
    int lane = t & 31, wid = t >> 5;

    __shared__ int rs[8];
    __shared__ int s_off;
    int acc = 0;
    for (int j = t; j < (int)blockIdx.x; j += 256) acc += g_bsum[j];
    #pragma unroll
    for (int off = 16; off > 0; off >>= 1)
        acc += __shfl_down_sync(0xffffffffu, acc, off);
    if (lane == 0) rs[wid] = acc;
    __syncthreads();
    if (t < 8) {
        int v = rs[t];
        #pragma unroll
        for (int off = 4; off > 0; off >>= 1)
            v += __shfl_down_sync(0xffu, v, off);
        if (t == 0) s_off = v;
    }
    __syncthreads();

    int i = blockIdx.x * 256 + t;
    int d = (i < NN) ? g_indeg_i[i] : 0;
    int v = d;
    #pragma unroll
    for (int off = 1; off < 32; off <<= 1) {
        int n = __shfl_up_sync(0xffffffffu, v, off);
        if (lane >= off) v += n;
    }
    __shared__ int ws[8];
    if (lane == 31) ws[wid] = v;
    __syncthreads();
    if (t < 8) {
        int s = ws[t];
        #pragma unroll
        for (int off = 1; off < 8; off <<= 1) {
            int n = __shfl_up_sync(0xffu, s, off);
            if (t >= off) s += n;
        }
        ws[t] = s;
    }
    __syncthreads();
    int inc = v + (wid > 0 ? ws[wid - 1] : 0) + s_off;
    int exc = inc - d;
    if (i < NN) {
        g_rowptr[i] = exc;
        g_cursor[i] = exc;
        g_outnorm[i] = rsqrtf(fmaxf((float)g_outdeg_i[i], 1.f));
    }
    if (i == NN) g_rowptr[NN] = NE;
}

// ---------------- fill dst-sorted edge list ----------------
__global__ void fill_kernel(const void* src, const void* dst) {
    int e = blockIdx.x * blockDim.x + threadIdx.x;
    if (e >= NE) return;
    int is64 = g_is64;
    int s = idx_at(src, e, is64);
    int d = idx_at(dst, e, is64);
    int pos = atomicAdd(&g_cursor[d], 1);
    g_esrc[pos] = s;
}

// ------- gather: one warp per dst node, shfl indices, 4 rows in flight -------
// A16[d] = fp16( in_norm(d) * sum_{e} out_norm(src) * feat[src] )
__global__ void gather_kernel(const float* __restrict__ feat) {
    int w = (blockIdx.x * blockDim.x + threadIdx.x) >> 5;
    if (w >= NN) return;
    int lane = threadIdx.x & 31;
    int beg = g_rowptr[w], end = g_rowptr[w + 1];

    const float4* f4 = (const float4*)feat;
    float4 a0 = make_float4(0.f, 0.f, 0.f, 0.f);
    float4 a1 = make_float4(0.f, 0.f, 0.f, 0.f);

    for (int base = beg; base < end; base += 32) {
        int n = min(32, end - base);
        int sl = (base + lane < end) ? g_esrc[base + lane] : 0;
        int j = 0;
        for (; j + 4 <= n; j += 4) {
            int s0 = __shfl_sync(0xffffffffu, sl, j);
            int s1 = __shfl_sync(0xffffffffu, sl, j + 1);
            int s2 = __shfl_sync(0xffffffffu, sl, j + 2);
            int s3 = __shfl_sync(0xffffffffu, sl, j + 3);
            float on0 = g_outnorm[s0], on1 = g_outnorm[s1];
            float on2 = g_outnorm[s2], on3 = g_outnorm[s3];
            float4 v0 = f4[s0 * 32 + lane];
            float4 v1 = f4[s1 * 32 + lane];
            float4 v2 = f4[s2 * 32 + lane];
            float4 v3 = f4[s3 * 32 + lane];
            a0.x += v0.x * on0; a0.y += v0.y * on0; a0.z += v0.z * on0; a0.w += v0.w * on0;
            a1.x += v1.x * on1; a1.y += v1.y * on1; a1.z += v1.z * on1; a1.w += v1.w * on1;
            a0.x += v2.x * on2; a0.y += v2.y * on2; a0.z += v2.z * on2; a0.w += v2.w * on2;
            a1.x += v3.x * on3; a1.y += v3.y * on3; a1.z += v3.z * on3; a1.w += v3.w * on3;
        }
        for (; j < n; j++) {
            int s0 = __shfl_sync(0xffffffffu, sl, j);
            float on0 = g_outnorm[s0];
            float4 v0 = f4[s0 * 32 + lane];
            a0.x += v0.x * on0; a0.y += v0.y * on0; a0.z += v0.z * on0; a0.w += v0.w * on0;
        }
    }
    float inn = rsqrtf(fmaxf((float)(end - beg), 1.f));
    __half2 h0 = __floats2half2_rn((a0.x + a1.x) * inn, (a0.y + a1.y) * inn);
    __half2 h1 = __floats2half2_rn((a0.z + a1.z) * inn, (a0.w + a1.w) * inn);
    uint2 pk;
    pk.x = *reinterpret_cast<unsigned*>(&h0);
    pk.y = *reinterpret_cast<unsigned*>(&h1);
    g_A16[(size_t)w * 32 + lane] = pk;
}

// ------ WMMA fp16 GEMM + fused bias/relu/segment-pool epilogue --------------
// 128x128 tile, full K=128 in smem (fp16). 8 warps, warp-tile 32x64 (2x4 frags).
// smem: bias 512B + gid 512B + A 128x136 half + B 128x136 half = 70656 B
// -> 3 CTAs/SM (epilogue latency hidden by other CTAs' MMA phases).
#define HPAD 136                       // half stride per smem row (272 B)
#define CPAD 132                       // fp32 stride for epilogue reuse
#define SMEM_GEMM (1024 + 2 * 128 * HPAD * 2)   // 70656 B

__global__ __launch_bounds__(256)
void gemm_pool_kernel(const float* __restrict__ bias, const void* gids) {
    extern __shared__ unsigned char smraw[];
    float*  sBias = (float*)smraw;                    // 128 floats
    int*    sGid  = (int*)(smraw + 512);              // 128 ints
    __half* As = (__half*)(smraw + 1024);             // 128 x 136 half
    __half* Bs = As + 128 * HPAD;                     // 128 x 136 half (W[k][n])
    float*  Cs = (float*)(smraw + 1024);              // epilogue reuse (128x132 f32)

    int tid = threadIdx.x;
    int wid = tid >> 5;
    int m0 = blockIdx.x * 128;

    if (tid < 128) {
        sBias[tid] = bias[tid];
        int grow = m0 + tid;
        sGid[tid] = (grow < NN) ? idx_at(gids, grow, g_is64) : -1;
    }

    // A + B tiles: fp16 from gmem, 4096 uint2 each
    {
        const uint2* pa = g_A16 + (size_t)m0 * 32;
        #pragma unroll
        for (int i = 0; i < 16; i++) {
            int idx = tid + i * 256;      // 0..4095
            int r = idx >> 5, c = idx & 31;
            *reinterpret_cast<uint2*>(As + r * HPAD + c * 4) = pa[idx];
            *reinterpret_cast<uint2*>(Bs + r * HPAD + c * 4) = g_B16[idx];
        }
    }
    __syncthreads();

    int wm = (wid >> 1) * 32;   // 0,32,64,96
    int wn = (wid & 1) * 64;    // 0,64

    wmma::fragment<wmma::accumulator, 16, 16, 16, float> acc[2][4];
    #pragma unroll
    for (int i = 0; i < 2; i++)
        #pragma unroll
        for (int j = 0; j < 4; j++)
            wmma::fill_fragment(acc[i][j], 0.f);

    #pragma unroll
    for (int k0 = 0; k0 < DIM; k0 += 16) {
        wmma::fragment<wmma::matrix_a, 16, 16, 16, __half, wmma::row_major> a[2];
        wmma::fragment<wmma::matrix_b, 16, 16, 16, __half, wmma::row_major> b[4];
        #pragma unroll
        for (int i = 0; i < 2; i++)
            wmma::load_matrix_sync(a[i], As + (wm + i * 16) * HPAD + k0, HPAD);
        #pragma unroll
        for (int j = 0; j < 4; j++)
            wmma::load_matrix_sync(b[j], Bs + k0 * HPAD + wn + j * 16, HPAD);
        #pragma unroll
        for (int i = 0; i < 2; i++)
            #pragma unroll
            for (int j = 0; j < 4; j++)
                wmma::mma_sync(acc[i][j], a[i], b[j], acc[i][j]);
    }
    __syncthreads();   // done reading As/Bs; Cs aliases them

    #pragma unroll
    for (int i = 0; i < 2; i++)
        #pragma unroll
        for (int j = 0; j < 4; j++)
            wmma::store_matrix_sync(Cs + (wm + i * 16) * CPAD + wn + j * 16,
                                    acc[i][j], CPAD, wmma::mem_row_major);
    __syncthreads();

    // fused bias + relu + segmented row-sum by graph id -> atomic pool accum
    // (graph_ids sorted ascending => ~2 segments per 64-row half)
    {
        int c = tid & 127;
        int half = tid >> 7;          // 0..1 -> rows [half*64, half*64+64)
        int r = half * 64;
        int rend = r + 64;
        float bv = sBias[c];
        if (m0 + r < NN) {
            int cur = sGid[r];
            float run = 0.f;
            for (; r < rend; r++) {
                if (m0 + r >= NN) break;
                int g = sGid[r];
                if (g != cur) {
                    atomicAdd(&g_pool[cur * DIM + c], run);
                    run = 0.f; cur = g;
                }
                run += fmaxf(Cs[r * CPAD + c] + bv, 0.f);
            }
            atomicAdd(&g_pool[cur * DIM + c], run);
        }
    }
}

// ---------------- head: out = (pool/cnt) @ Wh + bh ----------------
__global__ void head_kernel(const float* __restrict__ Wh,
                            const float* __restrict__ bh,
                            float* __restrict__ out) {
    __shared__ float pooled[DIM];
    int g = blockIdx.x;
    int c = threadIdx.x;
    float cnt = fmaxf((float)(g_start[g + 1] - g_start[g]), 1.f);
    pooled[c] = g_pool[g * DIM + c] / cnt;
    __syncthreads();
    if (c < NCLS) {
        float acc = bh[c];
        #pragma unroll 4
        for (int d = 0; d < DIM; d++) acc += pooled[d] * Wh[d * NCLS + c];
        out[g * NCLS + c] = acc;
    }
}

// ---------------- launch ----------------
extern "C" void kernel_launch(void* const* d_in, const int* in_sizes, int n_in,
                              void* d_out, int out_size) {
    const float* feat = (const float*)d_in[0];
    const void*  src  = d_in[1];
    const void*  dst  = d_in[2];
    const void*  gids = d_in[3];
    const float* W    = (const float*)d_in[4];
    const float* b    = (const float*)d_in[5];
    const float* Wh   = (const float*)d_in[6];
    const float* bh   = (const float*)d_in[7];
    float* out = (float*)d_out;

    cudaFuncSetAttribute(gemm_pool_kernel,
                         cudaFuncAttributeMaxDynamicSharedMemorySize, SMEM_GEMM);

    zero_bounds_kernel<<<(NN + 255) / 256, 256>>>(src, gids, W);
    degree_kernel<<<(NE + 255) / 256, 256>>>(src, dst);
    scan_partial_kernel<<<SB, 256>>>();
    scan_apply_kernel<<<SB + 1, 256>>>();
    fill_kernel<<<(NE + 255) / 256, 256>>>(src, dst);
    gather_kernel<<<(NN * 32 + 255) / 256, 256>>>(feat);
    gemm_pool_kernel<<<NT, 256, SMEM_GEMM>>>(b, gids);
    head_kernel<<<NG, DIM>>>(Wh, bh, out);
}